// round 12
// baseline (speedup 1.0000x reference)
#include <cuda_runtime.h>
#include <math_constants.h>

// RoIPool: input (N=2, C=256, H=50, W=50) f32, rois (K=256, 5) f32
// output (K, C, 7, 7) f32. scale = 0.0625, P = 7.
//
// R11 = R10 (ph-uniform work order, CPT=4, smem-hoisted bounds) +
// __launch_bounds__(256, 8): force <=32 regs so 8 blocks/SM fit
// (R10 sat at regs=38 -> 6 blocks -> occ 61%, issue 36%: latency-bound).
// More resident warps -> more loads in flight -> gather latency hidden.

#define P 7
#define PP 49
#define C_DIM 256
#define H_DIM 50
#define W_DIM 50
#define HW 2500
#define SCALE 0.0625f
#define ELEMS (C_DIM * PP)          // 12544 outputs per ROI
#define CPT 4                       // channels per thread
#define NCG (C_DIM / CPT)           // 64 channel groups
#define WORK_PER_ROI (P * NCG * P)  // 3136
#define BLOCKS_PER_ROI 13           // 13*256 = 3328 >= 3136
#define SPAN 4

__global__ __launch_bounds__(256, 8) void roipool_kernel(const float* __restrict__ x,
                                                         const float* __restrict__ rois,
                                                         float* __restrict__ out)
{
    const int k    = blockIdx.x / BLOCKS_PER_ROI;
    const int part = blockIdx.x - k * BLOCKS_PER_ROI;

    __shared__ int s_hs[P], s_he[P], s_ws[P], s_we[P];
    __shared__ int s_b;

    if (threadIdx.x < P) {
        const float* r = rois + k * 5;
        float x1 = rintf(r[1] * SCALE);
        float y1 = rintf(r[2] * SCALE);
        float x2 = rintf(r[3] * SCALE);
        float y2 = rintf(r[4] * SCALE);

        float bin_w = fmaxf(x2 - x1 + 1.0f, 1.0f) * (1.0f / P);
        float bin_h = fmaxf(y2 - y1 + 1.0f, 1.0f) * (1.0f / P);

        float p = (float)threadIdx.x;
        s_hs[threadIdx.x] = (int)fminf(fmaxf(floorf(p * bin_h) + y1, 0.0f), (float)H_DIM);
        s_he[threadIdx.x] = (int)fminf(fmaxf(ceilf((p + 1.0f) * bin_h) + y1, 0.0f), (float)H_DIM);
        s_ws[threadIdx.x] = (int)fminf(fmaxf(floorf(p * bin_w) + x1, 0.0f), (float)W_DIM);
        s_we[threadIdx.x] = (int)fminf(fmaxf(ceilf((p + 1.0f) * bin_w) + x1, 0.0f), (float)W_DIM);
        if (threadIdx.x == 0) s_b = (int)rois[k * 5];
    }
    __syncthreads();

    const int i = part * 256 + threadIdx.x;
    if (i >= WORK_PER_ROI) return;

    // (ph, cg, pw), ph slowest: 448 = 14 warps per ph -> warp-uniform ph.
    const int ph  = i / (NCG * P);
    const int rem = i - ph * (NCG * P);
    const int cg  = rem / P;
    const int pw  = rem - cg * P;

    const int hs = s_hs[ph], he = s_he[ph];      // warp-uniform
    const int ws = s_ws[pw], we = s_we[pw];
    const bool valid = (he > hs) && (we > ws);

    const float* base = x + ((size_t)s_b * C_DIM + cg * CPT) * HW;

    float m[CPT];
    #pragma unroll
    for (int ch = 0; ch < CPT; ++ch) m[ch] = -CUDART_INF_F;

    if (he - hs <= SPAN && we - ws <= SPAN) {
        // Fast path: uniform h branches, predicated 4-wide window.
        #pragma unroll
        for (int dh = 0; dh < SPAN; ++dh) {
            if (hs + dh < he) {                     // warp-uniform branch
                const float* row = base + (hs + dh) * W_DIM + ws;
                #pragma unroll
                for (int dw = 0; dw < SPAN; ++dw) {
                    const bool ok = (ws + dw < we);
                    #pragma unroll
                    for (int ch = 0; ch < CPT; ++ch) {
                        if (ok) m[ch] = fmaxf(m[ch], row[ch * HW + dw]);
                    }
                }
            }
        }
    } else {
        // Fallback: dynamic bounds (not hit by this data distribution).
        for (int h = hs; h < he; ++h) {
            const float* row = base + h * W_DIM;
            for (int w = ws; w < we; ++w) {
                #pragma unroll
                for (int ch = 0; ch < CPT; ++ch) {
                    m[ch] = fmaxf(m[ch], row[ch * HW + w]);
                }
            }
        }
    }

    float* o = out + (size_t)k * ELEMS + (size_t)(cg * CPT) * PP + ph * P + pw;
    #pragma unroll
    for (int ch = 0; ch < CPT; ++ch) {
        o[ch * PP] = valid ? m[ch] : 0.0f;
    }
}

extern "C" void kernel_launch(void* const* d_in, const int* in_sizes, int n_in,
                              void* d_out, int out_size)
{
    const float* x    = (const float*)d_in[0];
    const float* rois = (const float*)d_in[1];
    float* out        = (float*)d_out;

    int K = out_size / ELEMS;   // 256
    roipool_kernel<<<K * BLOCKS_PER_ROI, 256>>>(x, rois, out);
}

// round 13
// speedup vs baseline: 1.6243x; 1.6243x over previous
#include <cuda_runtime.h>
#include <math_constants.h>

// RoIPool: input (N=2, C=256, H=50, W=50) f32, rois (K=256, 5) f32
// output (K, C, 7, 7) f32. scale = 0.0625, P = 7.
//
// R12 = R10 (ph-uniform work order, CPT=4, smem-hoisted bounds, natural
// regs=38) with 128-thread blocks: 13 blocks/SM (81% occ ceiling) vs
// R10's 6x256 (75%, 61% achieved) -- occupancy recovered WITHOUT the
// register clamp that made R11 spill (L1 work +55%).

#define P 7
#define PP 49
#define C_DIM 256
#define H_DIM 50
#define W_DIM 50
#define HW 2500
#define SCALE 0.0625f
#define ELEMS (C_DIM * PP)          // 12544 outputs per ROI
#define CPT 4                       // channels per thread
#define NCG (C_DIM / CPT)           // 64 channel groups
#define WORK_PER_ROI (P * NCG * P)  // 3136
#define TPB 128
#define BLOCKS_PER_ROI 25           // 25*128 = 3200 >= 3136
#define SPAN 4

__global__ __launch_bounds__(TPB) void roipool_kernel(const float* __restrict__ x,
                                                      const float* __restrict__ rois,
                                                      float* __restrict__ out)
{
    const int k    = blockIdx.x / BLOCKS_PER_ROI;
    const int part = blockIdx.x - k * BLOCKS_PER_ROI;

    __shared__ int s_hs[P], s_he[P], s_ws[P], s_we[P];
    __shared__ int s_b;

    if (threadIdx.x < P) {
        const float* r = rois + k * 5;
        float x1 = rintf(r[1] * SCALE);
        float y1 = rintf(r[2] * SCALE);
        float x2 = rintf(r[3] * SCALE);
        float y2 = rintf(r[4] * SCALE);

        float bin_w = fmaxf(x2 - x1 + 1.0f, 1.0f) * (1.0f / P);
        float bin_h = fmaxf(y2 - y1 + 1.0f, 1.0f) * (1.0f / P);

        float p = (float)threadIdx.x;
        s_hs[threadIdx.x] = (int)fminf(fmaxf(floorf(p * bin_h) + y1, 0.0f), (float)H_DIM);
        s_he[threadIdx.x] = (int)fminf(fmaxf(ceilf((p + 1.0f) * bin_h) + y1, 0.0f), (float)H_DIM);
        s_ws[threadIdx.x] = (int)fminf(fmaxf(floorf(p * bin_w) + x1, 0.0f), (float)W_DIM);
        s_we[threadIdx.x] = (int)fminf(fmaxf(ceilf((p + 1.0f) * bin_w) + x1, 0.0f), (float)W_DIM);
        if (threadIdx.x == 0) s_b = (int)rois[k * 5];
    }
    __syncthreads();

    const int i = part * TPB + threadIdx.x;
    if (i >= WORK_PER_ROI) return;

    // (ph, cg, pw), ph slowest: 448 items per ph = 14 warps -> warp-uniform ph.
    const int ph  = i / (NCG * P);
    const int rem = i - ph * (NCG * P);
    const int cg  = rem / P;
    const int pw  = rem - cg * P;

    const int hs = s_hs[ph], he = s_he[ph];      // warp-uniform
    const int ws = s_ws[pw], we = s_we[pw];
    const bool valid = (he > hs) && (we > ws);

    const float* base = x + ((size_t)s_b * C_DIM + cg * CPT) * HW;

    float m[CPT];
    #pragma unroll
    for (int ch = 0; ch < CPT; ++ch) m[ch] = -CUDART_INF_F;

    if (he - hs <= SPAN && we - ws <= SPAN) {
        // Fast path: uniform h branches, predicated 4-wide window.
        #pragma unroll
        for (int dh = 0; dh < SPAN; ++dh) {
            if (hs + dh < he) {                     // warp-uniform branch
                const float* row = base + (hs + dh) * W_DIM + ws;
                #pragma unroll
                for (int dw = 0; dw < SPAN; ++dw) {
                    const bool ok = (ws + dw < we);
                    #pragma unroll
                    for (int ch = 0; ch < CPT; ++ch) {
                        if (ok) m[ch] = fmaxf(m[ch], row[ch * HW + dw]);
                    }
                }
            }
        }
    } else {
        // Fallback: dynamic bounds (not hit by this data distribution).
        for (int h = hs; h < he; ++h) {
            const float* row = base + h * W_DIM;
            for (int w = ws; w < we; ++w) {
                #pragma unroll
                for (int ch = 0; ch < CPT; ++ch) {
                    m[ch] = fmaxf(m[ch], row[ch * HW + w]);
                }
            }
        }
    }

    float* o = out + (size_t)k * ELEMS + (size_t)(cg * CPT) * PP + ph * P + pw;
    #pragma unroll
    for (int ch = 0; ch < CPT; ++ch) {
        o[ch * PP] = valid ? m[ch] : 0.0f;
    }
}

extern "C" void kernel_launch(void* const* d_in, const int* in_sizes, int n_in,
                              void* d_out, int out_size)
{
    const float* x    = (const float*)d_in[0];
    const float* rois = (const float*)d_in[1];
    float* out        = (float*)d_out;

    int K = out_size / ELEMS;   // 256
    roipool_kernel<<<K * BLOCKS_PER_ROI, TPB>>>(x, rois, out);
}